// round 5
// baseline (speedup 1.0000x reference)
#include <cuda_runtime.h>
#include <cstddef>

#define HDIM 64
#define NU_MAX 100000
#define NP_MAX 50000

// ---------------- scratch (static device globals; no allocation) ----------------
__device__ float g_deg_u[NU_MAX];
__device__ float g_deg_p[NP_MAX];
__device__ float g_yu  [(size_t)NU_MAX * HDIM];
__device__ float g_yp  [(size_t)NP_MAX * HDIM];
__device__ float g_aggu[(size_t)NU_MAX * HDIM];
__device__ float g_aggp[(size_t)NP_MAX * HDIM];
__device__ float g_hu  [(size_t)NU_MAX * HDIM];
__device__ float g_hp  [(size_t)NP_MAX * HDIM];
__device__ float g_hu2 [(size_t)NU_MAX * HDIM];
__device__ float g_hp2 [(size_t)NP_MAX * HDIM];

// ---------------- degree counts (once; reused by both layers) ----------------
__global__ void degree_kernel(const int* __restrict__ src, const int* __restrict__ dst, int E) {
    int i = blockIdx.x * blockDim.x + threadIdx.x;
    int stride = gridDim.x * blockDim.x;
    for (int e = i; e < E; e += stride) {
        atomicAdd(&g_deg_u[src[e]], 1.0f);
        atomicAdd(&g_deg_p[dst[e]], 1.0f);
    }
}

// ---------------- fused row GEMM: out = X @ W (+ agg/deg)(+ bias)(relu) ----------------
// warp per row; W staged in smem; x loaded as float4 broadcast; lane owns cols {lane, lane+32}
template <int D>
__global__ void sage_gemm(const float* __restrict__ X, const float* __restrict__ W,
                          const float* __restrict__ bias, const float* __restrict__ agg,
                          const float* __restrict__ deg, float* __restrict__ out,
                          int N, int do_relu) {
    __shared__ float Ws[D * HDIM];
    for (int i = threadIdx.x; i < D * HDIM; i += blockDim.x) Ws[i] = W[i];
    __syncthreads();

    int lane  = threadIdx.x & 31;
    int warp  = (blockIdx.x * blockDim.x + threadIdx.x) >> 5;
    int nwarp = (gridDim.x * blockDim.x) >> 5;

    for (int row = warp; row < N; row += nwarp) {
        const float4* xr = (const float4*)(X + (size_t)row * D);
        float acc0 = 0.f, acc1 = 0.f;
#pragma unroll
        for (int k4 = 0; k4 < D / 4; ++k4) {
            float4 xv = __ldg(xr + k4);
            int k = k4 * 4;
            acc0 += xv.x * Ws[(k + 0) * HDIM + lane];
            acc1 += xv.x * Ws[(k + 0) * HDIM + 32 + lane];
            acc0 += xv.y * Ws[(k + 1) * HDIM + lane];
            acc1 += xv.y * Ws[(k + 1) * HDIM + 32 + lane];
            acc0 += xv.z * Ws[(k + 2) * HDIM + lane];
            acc1 += xv.z * Ws[(k + 2) * HDIM + 32 + lane];
            acc0 += xv.w * Ws[(k + 3) * HDIM + lane];
            acc1 += xv.w * Ws[(k + 3) * HDIM + 32 + lane];
        }
        if (agg != nullptr) {
            float sc = 1.0f / fmaxf(deg[row], 1.0f);
            acc0 += agg[(size_t)row * HDIM + lane] * sc;
            acc1 += agg[(size_t)row * HDIM + 32 + lane] * sc;
        }
        if (bias != nullptr) {
            acc0 += bias[lane];
            acc1 += bias[32 + lane];
        }
        if (do_relu) {
            acc0 = fmaxf(acc0, 0.f);
            acc1 = fmaxf(acc1, 0.f);
        }
        out[(size_t)row * HDIM + lane]      = acc0;
        out[(size_t)row * HDIM + 32 + lane] = acc1;
    }
}

// ---------------- bidirectional scatter: warp per edge ----------------
// aggp[dst] += yu[src]; aggu[src] += yp[dst]   (64 floats each, 2 per lane)
__global__ void scatter_kernel(const float* __restrict__ yu, const float* __restrict__ yp,
                               const int* __restrict__ src, const int* __restrict__ dst,
                               float* __restrict__ aggp, float* __restrict__ aggu, int E) {
    int lane  = threadIdx.x & 31;
    int warp  = (blockIdx.x * blockDim.x + threadIdx.x) >> 5;
    int nwarp = (gridDim.x * blockDim.x) >> 5;
    for (int e = warp; e < E; e += nwarp) {
        int s = __ldg(&src[e]);
        int d = __ldg(&dst[e]);
        float2 a = *(const float2*)(yu + (size_t)s * HDIM + 2 * lane);
        float2 b = *(const float2*)(yp + (size_t)d * HDIM + 2 * lane);
        float* pp = aggp + (size_t)d * HDIM + 2 * lane;
        float* pu = aggu + (size_t)s * HDIM + 2 * lane;
        atomicAdd(pp + 0, a.x);
        atomicAdd(pp + 1, a.y);
        atomicAdd(pu + 0, b.x);
        atomicAdd(pu + 1, b.y);
    }
}

// ---------------- classifier: warp per label edge, dot over 64 dims ----------------
__global__ void classify_kernel(const float* __restrict__ hu2, const float* __restrict__ hp2,
                                const int* __restrict__ lu, const int* __restrict__ lp,
                                float* __restrict__ out, int M) {
    int lane  = threadIdx.x & 31;
    int warp  = (blockIdx.x * blockDim.x + threadIdx.x) >> 5;
    int nwarp = (gridDim.x * blockDim.x) >> 5;
    for (int e = warp; e < M; e += nwarp) {
        int u = __ldg(&lu[e]);
        int p = __ldg(&lp[e]);
        float2 a = *(const float2*)(hu2 + (size_t)u * HDIM + 2 * lane);
        float2 b = *(const float2*)(hp2 + (size_t)p * HDIM + 2 * lane);
        float s = a.x * b.x + a.y * b.y;
#pragma unroll
        for (int off = 16; off; off >>= 1) s += __shfl_xor_sync(0xffffffffu, s, off);
        if (lane == 0) out[e] = s;
    }
}

extern "C" void kernel_launch(void* const* d_in, const int* in_sizes, int n_in,
                              void* d_out, int out_size) {
    const float* x_user    = (const float*)d_in[0];
    const float* x_product = (const float*)d_in[1];
    const float* W1bl = (const float*)d_in[2];
    const float* b1b  = (const float*)d_in[3];
    const float* W1br = (const float*)d_in[4];
    const float* W1rl = (const float*)d_in[5];
    const float* b1r  = (const float*)d_in[6];
    const float* W1rr = (const float*)d_in[7];
    const float* W2bl = (const float*)d_in[8];
    const float* b2b  = (const float*)d_in[9];
    const float* W2br = (const float*)d_in[10];
    const float* W2rl = (const float*)d_in[11];
    const float* b2r  = (const float*)d_in[12];
    const float* W2rr = (const float*)d_in[13];
    const int* esrc = (const int*)d_in[14];
    const int* edst = (const int*)d_in[15];
    const int* lu   = (const int*)d_in[16];
    const int* lp   = (const int*)d_in[17];

    int NU = in_sizes[0] / 64;
    int NP = in_sizes[1] / 128;
    int E  = in_sizes[14];
    int M  = in_sizes[16];

    float *deg_u, *deg_p, *yu, *yp, *aggu, *aggp, *hu, *hp, *hu2, *hp2;
    cudaGetSymbolAddress((void**)&deg_u, g_deg_u);
    cudaGetSymbolAddress((void**)&deg_p, g_deg_p);
    cudaGetSymbolAddress((void**)&yu,   g_yu);
    cudaGetSymbolAddress((void**)&yp,   g_yp);
    cudaGetSymbolAddress((void**)&aggu, g_aggu);
    cudaGetSymbolAddress((void**)&aggp, g_aggp);
    cudaGetSymbolAddress((void**)&hu,   g_hu);
    cudaGetSymbolAddress((void**)&hp,   g_hp);
    cudaGetSymbolAddress((void**)&hu2,  g_hu2);
    cudaGetSymbolAddress((void**)&hp2,  g_hp2);

    const size_t HB = (size_t)HDIM * sizeof(float);

    // degree counts (shared by both layers)
    cudaMemsetAsync(deg_u, 0, (size_t)NU * sizeof(float), 0);
    cudaMemsetAsync(deg_p, 0, (size_t)NP * sizeof(float), 0);
    degree_kernel<<<2048, 256>>>(esrc, edst, E);

    // ---- layer 1 ----
    // transform-then-aggregate (matmul commutes with mean)
    sage_gemm<64> <<<2048, 256>>>(x_user,    W1bl, nullptr, nullptr, nullptr, yu, NU, 0);
    sage_gemm<128><<<2048, 256>>>(x_product, W1rl, nullptr, nullptr, nullptr, yp, NP, 0);
    cudaMemsetAsync(aggp, 0, (size_t)NP * HB, 0);
    cudaMemsetAsync(aggu, 0, (size_t)NU * HB, 0);
    scatter_kernel<<<4096, 256>>>(yu, yp, esrc, edst, aggp, aggu, E);
    sage_gemm<128><<<2048, 256>>>(x_product, W1br, b1b, aggp, deg_p, hp, NP, 1);
    sage_gemm<64> <<<2048, 256>>>(x_user,    W1rr, b1r, aggu, deg_u, hu, NU, 1);

    // ---- layer 2 ----
    sage_gemm<64><<<2048, 256>>>(hu, W2bl, nullptr, nullptr, nullptr, yu, NU, 0);
    sage_gemm<64><<<2048, 256>>>(hp, W2rl, nullptr, nullptr, nullptr, yp, NP, 0);
    cudaMemsetAsync(aggp, 0, (size_t)NP * HB, 0);
    cudaMemsetAsync(aggu, 0, (size_t)NU * HB, 0);
    scatter_kernel<<<4096, 256>>>(yu, yp, esrc, edst, aggp, aggu, E);
    sage_gemm<64><<<2048, 256>>>(hp, W2br, b2b, aggp, deg_p, hp2, NP, 0);
    sage_gemm<64><<<2048, 256>>>(hu, W2rr, b2r, aggu, deg_u, hu2, NU, 0);

    // ---- classifier ----
    classify_kernel<<<4096, 256>>>(hu2, hp2, lu, lp, (float*)d_out, M);
}

// round 6
// speedup vs baseline: 1.1038x; 1.1038x over previous
#include <cuda_runtime.h>
#include <cuda_fp16.h>
#include <cstddef>

#define HDIM 64
#define NU_MAX 100000
#define NP_MAX 50000
#define E_MAX  2000000
#define SCAN_TILE 1024

// ---------------- scratch (static device globals; no allocation) ----------------
__device__ int    g_cnt_u[NU_MAX + 1];
__device__ int    g_cnt_p[NP_MAX + 1];
__device__ int    g_rp_u [NU_MAX + 1];
__device__ int    g_rp_p [NP_MAX + 1];
__device__ int    g_cur_u[NU_MAX];
__device__ int    g_cur_p[NP_MAX];
__device__ int    g_bsum [1025];
__device__ int    g_csr_u[E_MAX];   // per-user list of dst product ids
__device__ int    g_csr_p[E_MAX];   // per-product list of src user ids
__device__ __half g_yu_h[(size_t)NU_MAX * HDIM];
__device__ __half g_yp_h[(size_t)NP_MAX * HDIM];
__device__ float  g_aggu[(size_t)NU_MAX * HDIM];
__device__ float  g_aggp[(size_t)NP_MAX * HDIM];
__device__ float  g_hu  [(size_t)NU_MAX * HDIM];
__device__ float  g_hp  [(size_t)NP_MAX * HDIM];
__device__ float  g_hu2 [(size_t)NU_MAX * HDIM];
__device__ float  g_hp2 [(size_t)NP_MAX * HDIM];

// ---------------- degree counts (int) ----------------
__global__ void degree_kernel(const int* __restrict__ src, const int* __restrict__ dst,
                              int* __restrict__ cu, int* __restrict__ cp, int E) {
    int i = blockIdx.x * blockDim.x + threadIdx.x;
    int st = gridDim.x * blockDim.x;
    for (int e = i; e < E; e += st) {
        atomicAdd(&cu[src[e]], 1);
        atomicAdd(&cp[dst[e]], 1);
    }
}

// ---------------- exclusive scan (3-phase) ----------------
__global__ void scanA(const int* __restrict__ in, int* __restrict__ bsum, int n) {
    __shared__ int sh[256];
    int t = threadIdx.x, b = blockIdx.x;
    int base = b * SCAN_TILE;
    int s = 0;
    for (int i = t; i < SCAN_TILE; i += 256) {
        int idx = base + i;
        s += (idx < n) ? in[idx] : 0;
    }
    sh[t] = s; __syncthreads();
    for (int o = 128; o; o >>= 1) {
        if (t < o) sh[t] += sh[t + o];
        __syncthreads();
    }
    if (t == 0) bsum[b] = sh[0];
}

__global__ void scanB(int* __restrict__ bsum, int nb) {
    __shared__ int sh[1024];
    int t = threadIdx.x;
    int v = (t < nb) ? bsum[t] : 0;
    sh[t] = v; __syncthreads();
    for (int o = 1; o < 1024; o <<= 1) {
        int x = 0;
        if (t >= o) x = sh[t - o];
        __syncthreads();
        sh[t] += x;
        __syncthreads();
    }
    if (t < nb) bsum[t] = sh[t] - v;     // exclusive
    if (t == 0) bsum[nb] = sh[1023];     // grand total
}

__global__ void scanC(const int* __restrict__ in, const int* __restrict__ bsum,
                      int* __restrict__ rp, int n) {
    __shared__ int sh[256];
    int t = threadIdx.x, b = blockIdx.x;
    int base = b * SCAN_TILE;
    int i0 = base + t * 4;
    int v0 = (i0     < n) ? in[i0]     : 0;
    int v1 = (i0 + 1 < n) ? in[i0 + 1] : 0;
    int v2 = (i0 + 2 < n) ? in[i0 + 2] : 0;
    int v3 = (i0 + 3 < n) ? in[i0 + 3] : 0;
    int local = v0 + v1 + v2 + v3;
    sh[t] = local; __syncthreads();
    for (int o = 1; o < 256; o <<= 1) {
        int x = 0;
        if (t >= o) x = sh[t - o];
        __syncthreads();
        sh[t] += x;
        __syncthreads();
    }
    int run = bsum[b] + sh[t] - local;
    if (i0     < n) rp[i0]     = run; run += v0;
    if (i0 + 1 < n) rp[i0 + 1] = run; run += v1;
    if (i0 + 2 < n) rp[i0 + 2] = run; run += v2;
    if (i0 + 3 < n) rp[i0 + 3] = run;
    if (b == 0 && t == 0) rp[n] = bsum[gridDim.x];
}

// ---------------- CSR fill ----------------
__global__ void fill_csr(const int* __restrict__ src, const int* __restrict__ dst,
                         int* __restrict__ cu, int* __restrict__ cp,
                         int* __restrict__ csr_u, int* __restrict__ csr_p, int E) {
    int i = blockIdx.x * blockDim.x + threadIdx.x;
    int st = gridDim.x * blockDim.x;
    for (int e = i; e < E; e += st) {
        int s = src[e], d = dst[e];
        int p = atomicAdd(&cp[d], 1); csr_p[p] = s;
        int q = atomicAdd(&cu[s], 1); csr_u[q] = d;
    }
}

// ---------------- gather mean: warp per dst node, y in fp16 ----------------
__global__ void gather_mean(const __half* __restrict__ Y, const int* __restrict__ csr,
                            const int* __restrict__ rp, float* __restrict__ agg, int N) {
    int lane = threadIdx.x & 31;
    int warp = (blockIdx.x * blockDim.x + threadIdx.x) >> 5;
    int nw   = (gridDim.x * blockDim.x) >> 5;
    const __half2* Y2 = (const __half2*)Y;
    for (int d = warp; d < N; d += nw) {
        int b = rp[d], e = rp[d + 1];
        float ax = 0.f, ay = 0.f;
        int j = b;
        for (; j + 4 <= e; j += 4) {
            int s0 = __ldg(&csr[j]);
            int s1 = __ldg(&csr[j + 1]);
            int s2 = __ldg(&csr[j + 2]);
            int s3 = __ldg(&csr[j + 3]);
            float2 f0 = __half22float2(Y2[(size_t)s0 * 32 + lane]);
            float2 f1 = __half22float2(Y2[(size_t)s1 * 32 + lane]);
            float2 f2 = __half22float2(Y2[(size_t)s2 * 32 + lane]);
            float2 f3 = __half22float2(Y2[(size_t)s3 * 32 + lane]);
            ax += f0.x + f1.x + f2.x + f3.x;
            ay += f0.y + f1.y + f2.y + f3.y;
        }
        for (; j < e; j++) {
            int s = __ldg(&csr[j]);
            float2 f = __half22float2(Y2[(size_t)s * 32 + lane]);
            ax += f.x; ay += f.y;
        }
        float inv = 1.0f / fmaxf((float)(e - b), 1.0f);
        ((float2*)agg)[(size_t)d * 32 + lane] = make_float2(ax * inv, ay * inv);
    }
}

// ---------------- register-tiled GEMM: out[M,64] = X[M,K] @ W[K,64] (+agg)(+bias)(relu) ----
// 256 threads per block, 64x64 tile, 4x4 micro-tile per thread.
// W staged in smem (broadcast LDS.128 b-frags); X streamed to registers in 8-k chunks.
template <int K, bool HALF_OUT>
__global__ void gemm_tiled(const float* __restrict__ X, const float* __restrict__ W,
                           const float* __restrict__ bias, const float* __restrict__ agg,
                           float* __restrict__ outf, __half* __restrict__ outh,
                           int M, int relu) {
    __shared__ float Ws[K * 64];
    int t = threadIdx.x;
    // load W (contiguous, coalesced float4)
    {
        const float4* wsrc = (const float4*)W;
        float4* wdst = (float4*)Ws;
#pragma unroll
        for (int i = 0; i < K / 16; i++) wdst[t + i * 256] = wsrc[t + i * 256];
    }
    __syncthreads();

    int base = blockIdx.x * 64;
    int lane = t & 31, w = t >> 5;
    int warp_r = w & 1, warp_c = w >> 1;
    int tr = lane & 7, tc = lane >> 3;
    int r0 = warp_r * 32 + tr * 4;
    int c0 = warp_c * 16 + tc * 4;

    // row indices (clamped for OOB loads; stores are guarded)
    int rows[4];
#pragma unroll
    for (int i = 0; i < 4; i++) {
        int r = base + r0 + i;
        rows[i] = (r < M) ? r : (M - 1);
    }

    float acc[4][4];
#pragma unroll
    for (int i = 0; i < 4; i++)
#pragma unroll
        for (int j = 0; j < 4; j++) acc[i][j] = 0.f;

#pragma unroll
    for (int kc = 0; kc < K / 8; kc++) {
        float a[4][8];
#pragma unroll
        for (int i = 0; i < 4; i++) {
            const float4* xp = (const float4*)(X + (size_t)rows[i] * K + kc * 8);
            float4 v0 = __ldg(xp);
            float4 v1 = __ldg(xp + 1);
            a[i][0] = v0.x; a[i][1] = v0.y; a[i][2] = v0.z; a[i][3] = v0.w;
            a[i][4] = v1.x; a[i][5] = v1.y; a[i][6] = v1.z; a[i][7] = v1.w;
        }
#pragma unroll
        for (int kk = 0; kk < 8; kk++) {
            int k = kc * 8 + kk;
            float4 b = *(const float4*)(Ws + k * 64 + c0);
#pragma unroll
            for (int i = 0; i < 4; i++) {
                acc[i][0] += a[i][kk] * b.x;
                acc[i][1] += a[i][kk] * b.y;
                acc[i][2] += a[i][kk] * b.z;
                acc[i][3] += a[i][kk] * b.w;
            }
        }
    }

    float4 bv = make_float4(0.f, 0.f, 0.f, 0.f);
    if (bias) bv = *(const float4*)(bias + c0);
#pragma unroll
    for (int i = 0; i < 4; i++) {
        int row = base + r0 + i;
        if (row >= M) continue;
        float4 r = make_float4(acc[i][0], acc[i][1], acc[i][2], acc[i][3]);
        if (agg) {
            float4 av = *(const float4*)(agg + (size_t)row * 64 + c0);
            r.x += av.x; r.y += av.y; r.z += av.z; r.w += av.w;
        }
        r.x += bv.x; r.y += bv.y; r.z += bv.z; r.w += bv.w;
        if (relu) {
            r.x = fmaxf(r.x, 0.f); r.y = fmaxf(r.y, 0.f);
            r.z = fmaxf(r.z, 0.f); r.w = fmaxf(r.w, 0.f);
        }
        if (HALF_OUT) {
            __half2 p0 = __floats2half2_rn(r.x, r.y);
            __half2 p1 = __floats2half2_rn(r.z, r.w);
            uint2 u;
            u.x = *(unsigned*)&p0;
            u.y = *(unsigned*)&p1;
            *(uint2*)(outh + (size_t)row * 64 + c0) = u;
        } else {
            *(float4*)(outf + (size_t)row * 64 + c0) = r;
        }
    }
}

// ---------------- classifier: warp per label edge, dot over 64 dims ----------------
__global__ void classify_kernel(const float* __restrict__ hu2, const float* __restrict__ hp2,
                                const int* __restrict__ lu, const int* __restrict__ lp,
                                float* __restrict__ out, int M) {
    int lane = threadIdx.x & 31;
    int warp = (blockIdx.x * blockDim.x + threadIdx.x) >> 5;
    int nw   = (gridDim.x * blockDim.x) >> 5;
    for (int e = warp; e < M; e += nw) {
        int u = __ldg(&lu[e]);
        int p = __ldg(&lp[e]);
        float2 a = *(const float2*)(hu2 + (size_t)u * HDIM + 2 * lane);
        float2 b = *(const float2*)(hp2 + (size_t)p * HDIM + 2 * lane);
        float s = a.x * b.x + a.y * b.y;
#pragma unroll
        for (int off = 16; off; off >>= 1) s += __shfl_xor_sync(0xffffffffu, s, off);
        if (lane == 0) out[e] = s;
    }
}

extern "C" void kernel_launch(void* const* d_in, const int* in_sizes, int n_in,
                              void* d_out, int out_size) {
    const float* x_user    = (const float*)d_in[0];
    const float* x_product = (const float*)d_in[1];
    const float* W1bl = (const float*)d_in[2];
    const float* b1b  = (const float*)d_in[3];
    const float* W1br = (const float*)d_in[4];
    const float* W1rl = (const float*)d_in[5];
    const float* b1r  = (const float*)d_in[6];
    const float* W1rr = (const float*)d_in[7];
    const float* W2bl = (const float*)d_in[8];
    const float* b2b  = (const float*)d_in[9];
    const float* W2br = (const float*)d_in[10];
    const float* W2rl = (const float*)d_in[11];
    const float* b2r  = (const float*)d_in[12];
    const float* W2rr = (const float*)d_in[13];
    const int* esrc = (const int*)d_in[14];
    const int* edst = (const int*)d_in[15];
    const int* lu   = (const int*)d_in[16];
    const int* lp   = (const int*)d_in[17];

    int NU = in_sizes[0] / 64;
    int NP = in_sizes[1] / 128;
    int E  = in_sizes[14];
    int M  = in_sizes[16];

    int *cnt_u, *cnt_p, *rp_u, *rp_p, *cur_u, *cur_p, *bsum, *csr_u, *csr_p;
    __half *yu_h, *yp_h;
    float *aggu, *aggp, *hu, *hp, *hu2, *hp2;
    cudaGetSymbolAddress((void**)&cnt_u, g_cnt_u);
    cudaGetSymbolAddress((void**)&cnt_p, g_cnt_p);
    cudaGetSymbolAddress((void**)&rp_u,  g_rp_u);
    cudaGetSymbolAddress((void**)&rp_p,  g_rp_p);
    cudaGetSymbolAddress((void**)&cur_u, g_cur_u);
    cudaGetSymbolAddress((void**)&cur_p, g_cur_p);
    cudaGetSymbolAddress((void**)&bsum,  g_bsum);
    cudaGetSymbolAddress((void**)&csr_u, g_csr_u);
    cudaGetSymbolAddress((void**)&csr_p, g_csr_p);
    cudaGetSymbolAddress((void**)&yu_h,  g_yu_h);
    cudaGetSymbolAddress((void**)&yp_h,  g_yp_h);
    cudaGetSymbolAddress((void**)&aggu,  g_aggu);
    cudaGetSymbolAddress((void**)&aggp,  g_aggp);
    cudaGetSymbolAddress((void**)&hu,    g_hu);
    cudaGetSymbolAddress((void**)&hp,    g_hp);
    cudaGetSymbolAddress((void**)&hu2,   g_hu2);
    cudaGetSymbolAddress((void**)&hp2,   g_hp2);

    int gbu = (NU + 63) / 64;   // gemm grids
    int gbp = (NP + 63) / 64;
    int nbu = (NU + SCAN_TILE - 1) / SCAN_TILE;
    int nbp = (NP + SCAN_TILE - 1) / SCAN_TILE;

    // ---- CSR build (once; reused by both layers) ----
    cudaMemsetAsync(cnt_u, 0, (size_t)NU * sizeof(int), 0);
    cudaMemsetAsync(cnt_p, 0, (size_t)NP * sizeof(int), 0);
    degree_kernel<<<2048, 256>>>(esrc, edst, cnt_u, cnt_p, E);
    scanA<<<nbp, 256>>>(cnt_p, bsum, NP);
    scanB<<<1, 1024>>>(bsum, nbp);
    scanC<<<nbp, 256>>>(cnt_p, bsum, rp_p, NP);
    scanA<<<nbu, 256>>>(cnt_u, bsum, NU);
    scanB<<<1, 1024>>>(bsum, nbu);
    scanC<<<nbu, 256>>>(cnt_u, bsum, rp_u, NU);
    cudaMemcpyAsync(cur_p, rp_p, (size_t)NP * sizeof(int), cudaMemcpyDeviceToDevice, 0);
    cudaMemcpyAsync(cur_u, rp_u, (size_t)NU * sizeof(int), cudaMemcpyDeviceToDevice, 0);
    fill_csr<<<2048, 256>>>(esrc, edst, cur_u, cur_p, csr_u, csr_p, E);

    // ---- layer 1 (transform-then-aggregate: matmul commutes with mean) ----
    gemm_tiled<64,  true><<<gbu, 256>>>(x_user,    W1bl, nullptr, nullptr, nullptr, yu_h, NU, 0);
    gemm_tiled<128, true><<<gbp, 256>>>(x_product, W1rl, nullptr, nullptr, nullptr, yp_h, NP, 0);
    gather_mean<<<1024, 256>>>(yu_h, csr_p, rp_p, aggp, NP);
    gather_mean<<<2048, 256>>>(yp_h, csr_u, rp_u, aggu, NU);
    gemm_tiled<128, false><<<gbp, 256>>>(x_product, W1br, b1b, aggp, hp, nullptr, NP, 1);
    gemm_tiled<64,  false><<<gbu, 256>>>(x_user,    W1rr, b1r, aggu, hu, nullptr, NU, 1);

    // ---- layer 2 ----
    gemm_tiled<64, true><<<gbu, 256>>>(hu, W2bl, nullptr, nullptr, nullptr, yu_h, NU, 0);
    gemm_tiled<64, true><<<gbp, 256>>>(hp, W2rl, nullptr, nullptr, nullptr, yp_h, NP, 0);
    gather_mean<<<1024, 256>>>(yu_h, csr_p, rp_p, aggp, NP);
    gather_mean<<<2048, 256>>>(yp_h, csr_u, rp_u, aggu, NU);
    gemm_tiled<64, false><<<gbp, 256>>>(hp, W2br, b2b, aggp, hp2, nullptr, NP, 0);
    gemm_tiled<64, false><<<gbu, 256>>>(hu, W2rr, b2r, aggu, hu2, nullptr, NU, 0);

    // ---- classifier ----
    classify_kernel<<<4096, 256>>>(hu2, hp2, lu, lp, (float*)d_out, M);
}

// round 7
// speedup vs baseline: 2.5350x; 2.2966x over previous
#include <cuda_runtime.h>
#include <cuda_fp16.h>
#include <cstddef>

#define HDIM 64
#define NU_MAX 100000
#define NP_MAX 50000
#define NT_MAX (NU_MAX + NP_MAX)
#define E_MAX  2000000
#define SCAN_TILE 1024

// ---------------- scratch (static device globals; no allocation) ----------------
__device__ int    g_cnt[NT_MAX + 1];
__device__ int    g_rp [NT_MAX + 1];
__device__ int    g_cur[NT_MAX];
__device__ int    g_bsum[256];
__device__ int    g_csr[2 * E_MAX];
__device__ __half g_yu_h[(size_t)NU_MAX * HDIM];
__device__ __half g_yp_h[(size_t)NP_MAX * HDIM];
__device__ float  g_aggu[(size_t)NU_MAX * HDIM];
__device__ float  g_aggp[(size_t)NP_MAX * HDIM];
__device__ float  g_hu  [(size_t)NU_MAX * HDIM];
__device__ float  g_hp  [(size_t)NP_MAX * HDIM];
__device__ float  g_hu2 [(size_t)NU_MAX * HDIM];
__device__ float  g_hp2 [(size_t)NP_MAX * HDIM];

// ---------------- degree counts into combined [products | users] array ----------------
__global__ void degree_kernel(const int* __restrict__ src, const int* __restrict__ dst,
                              int* __restrict__ cnt, int NP, int E) {
    int i = blockIdx.x * blockDim.x + threadIdx.x;
    int st = gridDim.x * blockDim.x;
    for (int e = i; e < E; e += st) {
        atomicAdd(&cnt[__ldg(&dst[e])], 1);
        atomicAdd(&cnt[NP + __ldg(&src[e])], 1);
    }
}

// ---------------- scan phase A: per-tile sums ----------------
__global__ void scanA(const int* __restrict__ in, int* __restrict__ bsum, int n) {
    __shared__ int sh[256];
    int t = threadIdx.x, b = blockIdx.x;
    int base = b * SCAN_TILE;
    int s = 0;
    for (int i = t; i < SCAN_TILE; i += 256) {
        int idx = base + i;
        s += (idx < n) ? in[idx] : 0;
    }
    sh[t] = s; __syncthreads();
    for (int o = 128; o; o >>= 1) {
        if (t < o) sh[t] += sh[t + o];
        __syncthreads();
    }
    if (t == 0) bsum[b] = sh[0];
}

// ---------------- scan phase C: local offset recompute + tile scan; writes rp AND cur ----
__global__ void scanC2(const int* __restrict__ cnt, const int* __restrict__ bsum,
                       int* __restrict__ rp, int* __restrict__ cur, int n, int nb) {
    __shared__ int sh[256];
    __shared__ int s_off;
    int t = threadIdx.x, b = blockIdx.x;
    // offset = sum of bsum[0..b)
    int part = 0;
    for (int i = t; i < b; i += 256) part += bsum[i];
    sh[t] = part; __syncthreads();
    for (int o = 128; o; o >>= 1) {
        if (t < o) sh[t] += sh[t + o];
        __syncthreads();
    }
    if (t == 0) s_off = sh[0];
    __syncthreads();
    int off = s_off;
    __syncthreads();

    int base = b * SCAN_TILE;
    int i0 = base + t * 4;
    int v0 = (i0     < n) ? cnt[i0]     : 0;
    int v1 = (i0 + 1 < n) ? cnt[i0 + 1] : 0;
    int v2 = (i0 + 2 < n) ? cnt[i0 + 2] : 0;
    int v3 = (i0 + 3 < n) ? cnt[i0 + 3] : 0;
    int local = v0 + v1 + v2 + v3;
    sh[t] = local; __syncthreads();
    for (int o = 1; o < 256; o <<= 1) {
        int x = 0;
        if (t >= o) x = sh[t - o];
        __syncthreads();
        sh[t] += x;
        __syncthreads();
    }
    int run = off + sh[t] - local;
    if (i0     < n) { rp[i0]     = run; cur[i0]     = run; } run += v0;
    if (i0 + 1 < n) { rp[i0 + 1] = run; cur[i0 + 1] = run; } run += v1;
    if (i0 + 2 < n) { rp[i0 + 2] = run; cur[i0 + 2] = run; } run += v2;
    if (i0 + 3 < n) { rp[i0 + 3] = run; cur[i0 + 3] = run; }
    if (b == 0 && t == 0) {
        int tot = 0;
        for (int i = 0; i < nb; i++) tot += bsum[i];
        rp[n] = tot;
    }
}

// ---------------- CSR fill (combined csr of size 2E) ----------------
__global__ void fill_csr(const int* __restrict__ src, const int* __restrict__ dst,
                         int* __restrict__ cur, int* __restrict__ csr, int NP, int E) {
    int i = blockIdx.x * blockDim.x + threadIdx.x;
    int st = gridDim.x * blockDim.x;
    for (int e = i; e < E; e += st) {
        int s = __ldg(&src[e]), d = __ldg(&dst[e]);
        csr[atomicAdd(&cur[d], 1)]      = s;   // product d's neighbor list: user ids
        csr[atomicAdd(&cur[NP + s], 1)] = d;   // user s's neighbor list: product ids
    }
}

// ---------------- dual-segment smem-tiled GEMM ----------------
// out[M,64] = X[M,K] @ W[K,64] (+agg)(+bias)(relu); 64x64 tile per 256-thread block.
// W staged in smem row-major; X staged TRANSPOSED k-major (stride 65) so the
// a-fragment is a conflict-free broadcast LDS and X hits global exactly once.
struct Seg {
    const float* X; const float* W; const float* bias; const float* agg;
    float* outf; __half* outh; int M; int K; int relu;
};

__global__ void gemm_dual(Seg A, Seg B, int nblkA) {
    extern __shared__ float sm[];
    bool isA = (blockIdx.x < (unsigned)nblkA);
    Seg S = isA ? A : B;
    int base = (isA ? blockIdx.x : (blockIdx.x - nblkA)) * 64;
    const int K = S.K;
    float* Ws = sm;            // [K][64]
    float* Xs = sm + K * 64;   // [K][64] with row stride 65

    int t = threadIdx.x;
    for (int i = t; i < K * 16; i += 256)
        ((float4*)Ws)[i] = __ldg((const float4*)S.W + i);
    int nq = K >> 2;
    for (int i = t; i < 64 * nq; i += 256) {
        int r = i / nq, kq = i - r * nq;
        int row = base + r;
        if (row >= S.M) row = S.M - 1;
        float4 v = __ldg((const float4*)(S.X + (size_t)row * K) + kq);
        int k = kq * 4;
        Xs[(k + 0) * 65 + r] = v.x;
        Xs[(k + 1) * 65 + r] = v.y;
        Xs[(k + 2) * 65 + r] = v.z;
        Xs[(k + 3) * 65 + r] = v.w;
    }
    __syncthreads();

    int lane = t & 31, w = t >> 5;
    int r0 = (w & 1) * 32 + (lane & 7) * 4;
    int c0 = (w >> 1) * 16 + (lane >> 3) * 4;

    float acc[4][4];
#pragma unroll
    for (int i = 0; i < 4; i++)
#pragma unroll
        for (int j = 0; j < 4; j++) acc[i][j] = 0.f;

#pragma unroll 4
    for (int kk = 0; kk < K; kk++) {
        const float* xr = Xs + kk * 65 + r0;
        float a0 = xr[0], a1 = xr[1], a2 = xr[2], a3 = xr[3];
        float4 bb = *(const float4*)(Ws + kk * 64 + c0);
        acc[0][0] += a0 * bb.x; acc[0][1] += a0 * bb.y; acc[0][2] += a0 * bb.z; acc[0][3] += a0 * bb.w;
        acc[1][0] += a1 * bb.x; acc[1][1] += a1 * bb.y; acc[1][2] += a1 * bb.z; acc[1][3] += a1 * bb.w;
        acc[2][0] += a2 * bb.x; acc[2][1] += a2 * bb.y; acc[2][2] += a2 * bb.z; acc[2][3] += a2 * bb.w;
        acc[3][0] += a3 * bb.x; acc[3][1] += a3 * bb.y; acc[3][2] += a3 * bb.z; acc[3][3] += a3 * bb.w;
    }

    float4 bv = make_float4(0.f, 0.f, 0.f, 0.f);
    if (S.bias) bv = *(const float4*)(S.bias + c0);
#pragma unroll
    for (int i = 0; i < 4; i++) {
        int row = base + r0 + i;
        if (row >= S.M) continue;
        float4 r4 = make_float4(acc[i][0] + bv.x, acc[i][1] + bv.y,
                                acc[i][2] + bv.z, acc[i][3] + bv.w);
        if (S.agg) {
            float4 av = *(const float4*)(S.agg + (size_t)row * 64 + c0);
            r4.x += av.x; r4.y += av.y; r4.z += av.z; r4.w += av.w;
        }
        if (S.relu) {
            r4.x = fmaxf(r4.x, 0.f); r4.y = fmaxf(r4.y, 0.f);
            r4.z = fmaxf(r4.z, 0.f); r4.w = fmaxf(r4.w, 0.f);
        }
        if (S.outh) {
            __half2 h0 = __floats2half2_rn(r4.x, r4.y);
            __half2 h1 = __floats2half2_rn(r4.z, r4.w);
            uint2 u;
            u.x = *(unsigned*)&h0;
            u.y = *(unsigned*)&h1;
            *(uint2*)(S.outh + (size_t)row * 64 + c0) = u;
        } else {
            *(float4*)(S.outf + (size_t)row * 64 + c0) = r4;
        }
    }
}

// ---------------- combined gather-mean: warp per node, 2 edges in flight ----------------
// node g < NP: product -> gathers yu rows into aggp; g >= NP: user -> gathers yp into aggu.
__global__ void gather_mean(const __half* __restrict__ yu, const __half* __restrict__ yp,
                            const int* __restrict__ csr, const int* __restrict__ rp,
                            float* __restrict__ aggp, float* __restrict__ aggu,
                            int NP, int NT) {
    int lane = threadIdx.x & 31;
    int warp = (blockIdx.x * blockDim.x + threadIdx.x) >> 5;
    int nw   = (gridDim.x * blockDim.x) >> 5;
    int f = lane & 15, par = lane >> 4;
    for (int g = warp; g < NT; g += nw) {
        int b = rp[g], e = rp[g + 1];
        const uint2* Y = (const uint2*)((g < NP) ? yu : yp);
        float* out = (g < NP) ? (aggp + (size_t)g * 64) : (aggu + (size_t)(g - NP) * 64);
        float ax = 0.f, ay = 0.f, az = 0.f, aw = 0.f;
        int j = b + par;
        for (; j + 2 < e; j += 4) {
            int s0 = __ldg(&csr[j]);
            int s1 = __ldg(&csr[j + 2]);
            uint2 v0 = __ldg(&Y[(size_t)s0 * 16 + f]);
            uint2 v1 = __ldg(&Y[(size_t)s1 * 16 + f]);
            float2 p0 = __half22float2(*(__half2*)&v0.x);
            float2 p1 = __half22float2(*(__half2*)&v0.y);
            float2 q0 = __half22float2(*(__half2*)&v1.x);
            float2 q1 = __half22float2(*(__half2*)&v1.y);
            ax += p0.x + q0.x; ay += p0.y + q0.y;
            az += p1.x + q1.x; aw += p1.y + q1.y;
        }
        if (j < e) {
            int s0 = __ldg(&csr[j]);
            uint2 v0 = __ldg(&Y[(size_t)s0 * 16 + f]);
            float2 p0 = __half22float2(*(__half2*)&v0.x);
            float2 p1 = __half22float2(*(__half2*)&v0.y);
            ax += p0.x; ay += p0.y; az += p1.x; aw += p1.y;
        }
        ax += __shfl_xor_sync(0xffffffffu, ax, 16);
        ay += __shfl_xor_sync(0xffffffffu, ay, 16);
        az += __shfl_xor_sync(0xffffffffu, az, 16);
        aw += __shfl_xor_sync(0xffffffffu, aw, 16);
        if (par == 0) {
            float inv = 1.0f / fmaxf((float)(e - b), 1.0f);
            ((float4*)out)[f] = make_float4(ax * inv, ay * inv, az * inv, aw * inv);
        }
    }
}

// ---------------- classifier: 2 label-edges per warp ----------------
__global__ void classify_kernel(const float* __restrict__ hu2, const float* __restrict__ hp2,
                                const int* __restrict__ lu, const int* __restrict__ lp,
                                float* __restrict__ out, int M) {
    int lane = threadIdx.x & 31;
    int warp = (blockIdx.x * blockDim.x + threadIdx.x) >> 5;
    int nw   = (gridDim.x * blockDim.x) >> 5;
    int f = lane & 15, par = lane >> 4;
    for (int e0 = warp * 2; e0 < M; e0 += nw * 2) {
        int e = e0 + par;
        float s = 0.f;
        if (e < M) {
            int u = __ldg(&lu[e]), p = __ldg(&lp[e]);
            float4 a  = __ldg((const float4*)(hu2 + (size_t)u * 64) + f);
            float4 bq = __ldg((const float4*)(hp2 + (size_t)p * 64) + f);
            s = a.x * bq.x + a.y * bq.y + a.z * bq.z + a.w * bq.w;
        }
        s += __shfl_xor_sync(0xffffffffu, s, 8);
        s += __shfl_xor_sync(0xffffffffu, s, 4);
        s += __shfl_xor_sync(0xffffffffu, s, 2);
        s += __shfl_xor_sync(0xffffffffu, s, 1);
        if (f == 0 && e < M) out[e] = s;
    }
}

extern "C" void kernel_launch(void* const* d_in, const int* in_sizes, int n_in,
                              void* d_out, int out_size) {
    const float* x_user    = (const float*)d_in[0];
    const float* x_product = (const float*)d_in[1];
    const float* W1bl = (const float*)d_in[2];
    const float* b1b  = (const float*)d_in[3];
    const float* W1br = (const float*)d_in[4];
    const float* W1rl = (const float*)d_in[5];
    const float* b1r  = (const float*)d_in[6];
    const float* W1rr = (const float*)d_in[7];
    const float* W2bl = (const float*)d_in[8];
    const float* b2b  = (const float*)d_in[9];
    const float* W2br = (const float*)d_in[10];
    const float* W2rl = (const float*)d_in[11];
    const float* b2r  = (const float*)d_in[12];
    const float* W2rr = (const float*)d_in[13];
    const int* esrc = (const int*)d_in[14];
    const int* edst = (const int*)d_in[15];
    const int* lu   = (const int*)d_in[16];
    const int* lp   = (const int*)d_in[17];

    int NU = in_sizes[0] / 64;
    int NP = in_sizes[1] / 128;
    int E  = in_sizes[14];
    int M  = in_sizes[16];
    int NT = NU + NP;

    int *cnt, *rp, *cur, *bsum, *csr;
    __half *yu_h, *yp_h;
    float *aggu, *aggp, *hu, *hp, *hu2, *hp2;
    cudaGetSymbolAddress((void**)&cnt,  g_cnt);
    cudaGetSymbolAddress((void**)&rp,   g_rp);
    cudaGetSymbolAddress((void**)&cur,  g_cur);
    cudaGetSymbolAddress((void**)&bsum, g_bsum);
    cudaGetSymbolAddress((void**)&csr,  g_csr);
    cudaGetSymbolAddress((void**)&yu_h, g_yu_h);
    cudaGetSymbolAddress((void**)&yp_h, g_yp_h);
    cudaGetSymbolAddress((void**)&aggu, g_aggu);
    cudaGetSymbolAddress((void**)&aggp, g_aggp);
    cudaGetSymbolAddress((void**)&hu,   g_hu);
    cudaGetSymbolAddress((void**)&hp,   g_hp);
    cudaGetSymbolAddress((void**)&hu2,  g_hu2);
    cudaGetSymbolAddress((void**)&hp2,  g_hp2);

    // allow 64KB+ dynamic smem for the GEMM (idempotent)
    cudaFuncSetAttribute(gemm_dual, cudaFuncAttributeMaxDynamicSharedMemorySize, 66048);

    int nblkP = (NP + 63) / 64;
    int nblkU = (NU + 63) / 64;
    int nbt   = (NT + SCAN_TILE - 1) / SCAN_TILE;
    size_t smemL1 = 128 * 129 * sizeof(float);   // maxK=128 tiles
    size_t smemL2 = 64 * 129 * sizeof(float);    // K=64 tiles

    // ---- CSR build (5 launches, reused by both layers) ----
    cudaMemsetAsync(cnt, 0, (size_t)NT * sizeof(int), 0);
    degree_kernel<<<2048, 256>>>(esrc, edst, cnt, NP, E);
    scanA<<<nbt, 256>>>(cnt, bsum, NT);
    scanC2<<<nbt, 256>>>(cnt, bsum, rp, cur, NT, nbt);
    fill_csr<<<2048, 256>>>(esrc, edst, cur, csr, NP, E);

    Seg nil = {};

    // ---- layer 1: transform (matmul commutes with mean), gather, epilogue ----
    {
        Seg A = {x_product, W1rl, nullptr, nullptr, nullptr, yp_h, NP, 128, 0};
        Seg B = {x_user,    W1bl, nullptr, nullptr, nullptr, yu_h, NU, 64,  0};
        gemm_dual<<<nblkP + nblkU, 256, smemL1>>>(A, B, nblkP);
    }
    gather_mean<<<2048, 256>>>(yu_h, yp_h, csr, rp, aggp, aggu, NP, NT);
    {
        Seg A = {x_product, W1br, b1b, aggp, hp, nullptr, NP, 128, 1};
        Seg B = {x_user,    W1rr, b1r, aggu, hu, nullptr, NU, 64,  1};
        gemm_dual<<<nblkP + nblkU, 256, smemL1>>>(A, B, nblkP);
    }

    // ---- layer 2 ----
    {
        Seg A = {hp, W2rl, nullptr, nullptr, nullptr, yp_h, NP, 64, 0};
        Seg B = {hu, W2bl, nullptr, nullptr, nullptr, yu_h, NU, 64, 0};
        gemm_dual<<<nblkP + nblkU, 256, smemL2>>>(A, B, nblkP);
    }
    gather_mean<<<2048, 256>>>(yu_h, yp_h, csr, rp, aggp, aggu, NP, NT);
    {
        Seg A = {hp, W2br, b2b, aggp, hp2, nullptr, NP, 64, 0};
        Seg B = {hu, W2rr, b2r, aggu, hu2, nullptr, NU, 64, 0};
        gemm_dual<<<nblkP + nblkU, 256, smemL2>>>(A, B, nblkP);
    }

    // ---- classifier ----
    classify_kernel<<<4096, 256>>>(hu2, hp2, lu, lp, (float*)d_out, M);
    (void)nil;
}